// round 16
// baseline (speedup 1.0000x reference)
#include <cuda_runtime.h>
#include <cuda_fp16.h>
#include <cstdint>

#define BSZ 4
#define SEQ 2048
#define DIM 1024
#define MTOT (BSZ*SEQ)

// ---------------------------------------------------------------------------
// HALF packed layout everywhere: per row of K floats, K/32 chunks of 64B
// [32 fp16], row stride K*2 bytes.
// ---------------------------------------------------------------------------
__device__ __align__(128) char g_xpk   [(size_t)MTOT * DIM * 2];
__device__ __align__(128) char g_wpk   [(size_t)3 * DIM * DIM * 2];
__device__ __align__(128) char g_w1pk  [(size_t)DIM * 2 * DIM * 2];
__device__ __align__(128) char g_w2pk  [(size_t)DIM * DIM * 2];
__device__ __align__(128) char g_qkvpk [(size_t)3 * MTOT * DIM * 2];  // q|k|v
__device__ __align__(128) char g_scores[(size_t)BSZ * SEQ * SEQ * 2]; // fp16
__device__ __align__(128) char g_ppk   [(size_t)BSZ * SEQ * SEQ * 2];
__device__ __align__(128) char g_apk   [(size_t)MTOT * DIM * 2];
__device__ __align__(128) char g_hpk   [(size_t)MTOT * DIM * 2];

// ---------------------------------------------------------------------------
// Helpers
// ---------------------------------------------------------------------------
__device__ __forceinline__ uint32_t smem_u32(const void* p) {
    uint32_t a;
    asm("{ .reg .u64 t; cvta.to.shared.u64 t, %1; cvt.u32.u64 %0, t; }" : "=r"(a) : "l"(p));
    return a;
}
__device__ __forceinline__ uint32_t swz(uint32_t x) { return x ^ ((x >> 3) & 0x70); }

__device__ __forceinline__ uint32_t f16pair(float v0, float v1) {
    uint32_t r;   // low16 = fp16(v0), high16 = fp16(v1)
    asm("cvt.rn.f16x2.f32 %0, %1, %2;" : "=r"(r) : "f"(v1), "f"(v0));
    return r;
}
__device__ __forceinline__ void ldsm4(uint32_t* r, uint32_t addr) {
    asm volatile("ldmatrix.sync.aligned.m8n8.x4.shared.b16 {%0,%1,%2,%3}, [%4];"
                 : "=r"(r[0]), "=r"(r[1]), "=r"(r[2]), "=r"(r[3]) : "r"(addr));
}
__device__ __forceinline__ void ldsm4t(uint32_t* r, uint32_t addr) {
    asm volatile("ldmatrix.sync.aligned.m8n8.x4.trans.shared.b16 {%0,%1,%2,%3}, [%4];"
                 : "=r"(r[0]), "=r"(r[1]), "=r"(r[2]), "=r"(r[3]) : "r"(addr));
}
__device__ __forceinline__ void mma_f16(float* d, const uint32_t* a, const uint32_t* b) {
    asm volatile(
        "mma.sync.aligned.m16n8k16.row.col.f32.f16.f16.f32 "
        "{%0,%1,%2,%3}, {%4,%5,%6,%7}, {%8,%9}, {%0,%1,%2,%3};"
        : "+f"(d[0]), "+f"(d[1]), "+f"(d[2]), "+f"(d[3])
        : "r"(a[0]), "r"(a[1]), "r"(a[2]), "r"(a[3]), "r"(b[0]), "r"(b[1]));
}

// ---------------------------------------------------------------------------
// NT GEMM, 128(M)x64(N) tile, 8 warps (32x32 each), pure fp16 operands,
// fp32 accumulate. 3-stage cp.async pipeline, 1 sync/chunk.
// BNN=0: B source K-major [n][k] (ldmatrix); BNN=1: B row-major [k][n]
//        (ldmatrix.trans; B tile = 32 k-rows x 128B contiguous n)
// mode: 1=relu, 4=causal k-limit, 16=half packed out,
//       32=triangular grid decode (blockIdx.x -> (x,y) lower-tri tiles)
// ---------------------------------------------------------------------------
#define TA_BYTES 16384
#define STG 24576
#define GEMM_SMEM (3 * STG)

template <int BNN>
__global__ __launch_bounds__(256, 3) void gemm_mma(
    const char* __restrict__ Ap, const char* __restrict__ Bp,
    long aRB, long bRB, long zsA, long zsB, int kc1,
    const char* __restrict__ Ap2, const char* __restrict__ Bp2,
    long aRB2, long bRB2, int kc2,
    void* Cout, long zsC, int ldc, long cRB,
    float scale, const float* __restrict__ bias, int mode)
{
    int m0, n0;
    if (mode & 32) {
        // triangular decode: live lower-tri tiles only.
        // y tile has 2y+2 x-tiles; cum(y) = y^2 + y.
        int t = blockIdx.x;
        float r = sqrtf(4.0f * (float)t + 1.0f);
        int y = (int)((r - 1.0f) * 0.5f);
        if (y * y + y > t) y--;
        if ((y + 1) * (y + 1) + (y + 1) <= t) y++;
        int xb = t - (y * y + y);
        m0 = y * 128;
        n0 = xb * 64;
    } else {
        m0 = blockIdx.y * 128;
        n0 = blockIdx.x * 64;
    }
    if (mode & 4) { int ke = (m0 + 128) >> 5; if (ke < kc1) kc1 = ke; }
    int z = blockIdx.z;
    Ap += (long)z * zsA;
    Bp += (long)z * zsB;
    char* Cb = (char*)Cout + (long)z * zsC;

    extern __shared__ char smem[];
    uint32_t sb = smem_u32(smem);
    int tid = threadIdx.x;
    int nch = kc1 + kc2;

    auto issue = [&](int c) {
        uint32_t stg = sb + (uint32_t)(c % 3) * STG;
        int cc = c;
        const char* pa; const char* pb; long ra, rb;
        if (c < kc1) { pa = Ap;  pb = Bp;  ra = aRB;  rb = bRB; }
        else         { pa = Ap2; pb = Bp2; ra = aRB2; rb = bRB2; cc = c - kc1; }
        long cOff = (long)cc * 64;
#pragma unroll
        for (int j = 0; j < 3; j++) {
            int slot = tid + j * 256;
            const char* g; uint32_t d;
            if (slot < 512) {
                int row = slot >> 2, seg = slot & 3;
                g = pa + (long)(m0 + row) * ra + cOff + seg * 16;
                d = stg + swz((uint32_t)(row * 128 + seg * 16));
            } else if (BNN) {
                int local = slot - 512;
                int row = local >> 3, seg = local & 7;
                g = pb + (long)(cc * 32 + row) * rb + (long)n0 * 2 + seg * 16;
                d = stg + (uint32_t)TA_BYTES + swz((uint32_t)(row * 128 + seg * 16));
            } else {
                int local = slot - 512;
                int row = local >> 2, seg = local & 3;
                g = pb + (long)(n0 + row) * rb + cOff + seg * 16;
                d = stg + (uint32_t)TA_BYTES + swz((uint32_t)(row * 128 + seg * 16));
            }
            asm volatile("cp.async.cg.shared.global [%0], [%1], 16;" :: "r"(d), "l"(g));
        }
        asm volatile("cp.async.commit_group;" ::: "memory");
    };

    int wid = tid >> 5, lane = tid & 31;
    int wm = wid >> 1, wn = wid & 1;   // 4 (m) x 2 (n) warps
    float acc[2][4][4] = {};

    issue(0);
    if (nch > 1) issue(1);
    else asm volatile("cp.async.commit_group;" ::: "memory");

    uint32_t aRowLoc = (uint32_t)((wm * 32 + (lane & 15)) * 128 + ((lane >> 4) << 4));
    int bg = lane >> 3;
    uint32_t bRowLoc = (uint32_t)((wn * 32 + (lane & 7) + ((bg >> 1) << 3)) * 128 + ((bg & 1) << 4));
    uint32_t bRowLocT = (uint32_t)((((lane >> 3) & 1) * 8 + (lane & 7)) * 128
                                   + wn * 64 + ((lane >> 4) << 4));

    for (int c = 0; c < nch; c++) {
        asm volatile("cp.async.wait_group 1;" ::: "memory");
        __syncthreads();
        if (c + 2 < nch) issue(c + 2);
        else asm volatile("cp.async.commit_group;" ::: "memory");

        uint32_t ta = sb + (uint32_t)(c % 3) * STG;
        uint32_t tb = ta + TA_BYTES;
#pragma unroll
        for (int s = 0; s < 2; s++) {
            int ko = s * 32;
            uint32_t Ah[2][4], Bh[2][4];
#pragma unroll
            for (int mt = 0; mt < 2; mt++)
                ldsm4(Ah[mt], ta + swz(aRowLoc + mt * 2048 + ko));
#pragma unroll
            for (int bt = 0; bt < 2; bt++) {
                if (BNN) ldsm4t(Bh[bt], tb + swz(bRowLocT + s * 2048 + bt * 32));
                else     ldsm4 (Bh[bt], tb + swz(bRowLoc + bt * 2048 + ko));
            }
#pragma unroll
            for (int mt = 0; mt < 2; mt++)
#pragma unroll
                for (int nt = 0; nt < 4; nt++)
                    mma_f16(acc[mt][nt], Ah[mt], &Bh[nt >> 1][(nt & 1) * 2]);
        }
    }

    // Epilogue
    int ql = lane & 3;
    int r0 = m0 + wm * 32 + (lane >> 2);
    if (mode & 16) {           // half packed out
        int cw = (n0 + wn * 32) >> 5;
        char* cbase = Cb + (long)cw * 64;
#pragma unroll
        for (int mt = 0; mt < 2; mt++) {
#pragma unroll
            for (int half = 0; half < 2; half++) {
                long row = r0 + mt * 16 + half * 8;
                char* rp = cbase + row * cRB;
#pragma unroll
                for (int nt = 0; nt < 4; nt++) {
                    float v0 = acc[mt][nt][half * 2 + 0] * scale;
                    float v1 = acc[mt][nt][half * 2 + 1] * scale;
                    int col = n0 + wn * 32 + nt * 8 + ql * 2;
                    if (bias) { v0 += bias[col]; v1 += bias[col + 1]; }
                    if (mode & 1) { v0 = fmaxf(v0, 0.f); v1 = fmaxf(v1, 0.f); }
                    *(uint32_t*)(rp + (nt * 8 + ql * 2) * 2) = f16pair(v0, v1);
                }
            }
        }
    } else {                   // fp32 out
        float* Cf = (float*)Cb;
#pragma unroll
        for (int mt = 0; mt < 2; mt++) {
#pragma unroll
            for (int half = 0; half < 2; half++) {
                long row = r0 + mt * 16 + half * 8;
#pragma unroll
                for (int nt = 0; nt < 4; nt++) {
                    float v0 = acc[mt][nt][half * 2 + 0] * scale;
                    float v1 = acc[mt][nt][half * 2 + 1] * scale;
                    int col = n0 + wn * 32 + nt * 8 + ql * 2;
                    if (bias) { v0 += bias[col]; v1 += bias[col + 1]; }
                    if (mode & 1) { v0 = fmaxf(v0, 0.f); v1 = fmaxf(v1, 0.f); }
                    *(float2*)(Cf + row * (long)ldc + col) = make_float2(v0, v1);
                }
            }
        }
    }
}

// ---------------------------------------------------------------------------
// Pack fp32 [rows][K] -> HALF packed
// ---------------------------------------------------------------------------
__global__ __launch_bounds__(256) void k_pack(const float* __restrict__ src,
                                              char* __restrict__ dst, int K) {
    long j0 = ((long)blockIdx.x * 256 + threadIdx.x) * 8;
    float4 f0 = *(const float4*)(src + j0);
    float4 f1 = *(const float4*)(src + j0 + 4);
    long row = j0 / K;
    int k0 = (int)(j0 - row * K);
    uint32_t h0 = f16pair(f0.x, f0.y), h1 = f16pair(f0.z, f0.w);
    uint32_t h2 = f16pair(f1.x, f1.y), h3 = f16pair(f1.z, f1.w);
    char* p = dst + row * (long)K * 2 + (k0 >> 5) * 64 + (k0 & 31) * 2;
    *(uint4*)p = make_uint4(h0, h1, h2, h3);
}

// ---------------------------------------------------------------------------
// ALL weight transposes in one launch (z: 0-2 Wq/Wk/Wv, 3 W2, 4 W1)
// ---------------------------------------------------------------------------
__global__ __launch_bounds__(256) void k_wtrans(
    const float* __restrict__ Wq, const float* __restrict__ Wk,
    const float* __restrict__ Wv, const float* __restrict__ W1,
    const float* __restrict__ W2,
    char* __restrict__ wpk, char* __restrict__ w1pk, char* __restrict__ w2pk)
{
    const long WPL = (long)DIM * DIM * 2;
    int z = blockIdx.z;
    const float* in; char* out; int R;
    if (z == 0)      { in = Wq; out = wpk;           R = DIM; }
    else if (z == 1) { in = Wk; out = wpk + WPL;     R = DIM; }
    else if (z == 2) { in = Wv; out = wpk + 2 * WPL; R = DIM; }
    else if (z == 3) { in = W2; out = w2pk;          R = DIM; }
    else             { in = W1; out = w1pk;          R = 2 * DIM; }
    int r0 = blockIdx.y * 32;
    if (r0 >= R) return;
    int c0 = blockIdx.x * 32;

    __shared__ float t[32][33];
    int tx = threadIdx.x & 31, ty = threadIdx.x >> 5;
#pragma unroll
    for (int i = ty; i < 32; i += 8)
        t[i][tx] = in[(long)(r0 + i) * DIM + c0 + tx];
    __syncthreads();
    int i = threadIdx.x >> 3;
    int g = (threadIdx.x & 7) * 4;
    float v0 = t[g + 0][i], v1 = t[g + 1][i], v2 = t[g + 2][i], v3 = t[g + 3][i];
    uint32_t h0 = f16pair(v0, v1), h1 = f16pair(v2, v3);
    char* p = out + (long)(c0 + i) * ((long)R * 2) + (r0 >> 5) * 64 + g * 2;
    *(uint2*)p = make_uint2(h0, h1);
}

// ---------------------------------------------------------------------------
// Causal softmax: HALF packed scores row -> HALF packed probs row
// ---------------------------------------------------------------------------
__global__ __launch_bounds__(256) void k_softmax() {
    long rowi = blockIdx.x;
    const char* p = g_scores + rowi * (SEQ * 2);
    char* dst = g_ppk + rowi * (SEQ * 2);
    int cnt = (int)(rowi & (SEQ - 1)) + 1;
    int tid = threadIdx.x;
    int j0 = tid * 8;
    __shared__ float red[256];

    uint4 raw = *(const uint4*)(p + (j0 >> 5) * 64 + (j0 & 31) * 2);
    __half* hp = (__half*)&raw;
    float v[8];
    float m = -3.4e38f;
#pragma unroll
    for (int i = 0; i < 8; i++) {
        v[i] = (j0 + i < cnt) ? __half2float(hp[i]) : -3.4e38f;
        m = fmaxf(m, v[i]);
    }
    red[tid] = m;
    __syncthreads();
    for (int s = 128; s > 0; s >>= 1) {
        if (tid < s) red[tid] = fmaxf(red[tid], red[tid + s]);
        __syncthreads();
    }
    m = red[0];
    __syncthreads();
    float sum = 0.f;
#pragma unroll
    for (int i = 0; i < 8; i++) {
        v[i] = (j0 + i < cnt) ? __expf(v[i] - m) : 0.f;
        sum += v[i];
    }
    red[tid] = sum;
    __syncthreads();
    for (int s = 128; s > 0; s >>= 1) {
        if (tid < s) red[tid] += red[tid + s];
        __syncthreads();
    }
    float inv = 1.0f / red[0];
#pragma unroll
    for (int i = 0; i < 8; i++) v[i] *= inv;

    uint32_t h0 = f16pair(v[0], v[1]), h1 = f16pair(v[2], v[3]);
    uint32_t h2 = f16pair(v[4], v[5]), h3 = f16pair(v[6], v[7]);
    char* q = dst + (j0 >> 5) * 64 + (j0 & 31) * 2;
    *(uint4*)q = make_uint4(h0, h1, h2, h3);
}

// ---------------------------------------------------------------------------
// Launch
// ---------------------------------------------------------------------------
extern "C" void kernel_launch(void* const* d_in, const int* in_sizes, int n_in,
                              void* d_out, int out_size) {
    const float* x  = (const float*)d_in[0];
    const float* Wq = (const float*)d_in[1];
    const float* Wk = (const float*)d_in[2];
    const float* Wv = (const float*)d_in[3];
    const float* W1 = (const float*)d_in[4];
    const float* b1 = (const float*)d_in[5];
    const float* W2 = (const float*)d_in[6];
    const float* b2 = (const float*)d_in[7];
    float* out = (float*)d_out;

    cudaFuncSetAttribute(gemm_mma<0>, cudaFuncAttributeMaxDynamicSharedMemorySize, GEMM_SMEM);
    cudaFuncSetAttribute(gemm_mma<1>, cudaFuncAttributeMaxDynamicSharedMemorySize, GEMM_SMEM);

    void* p;
    cudaGetSymbolAddress(&p, g_xpk);    char* xpk   = (char*)p;
    cudaGetSymbolAddress(&p, g_wpk);    char* wpk   = (char*)p;
    cudaGetSymbolAddress(&p, g_w1pk);   char* w1pk  = (char*)p;
    cudaGetSymbolAddress(&p, g_w2pk);   char* w2pk  = (char*)p;
    cudaGetSymbolAddress(&p, g_qkvpk);  char* qkvpk = (char*)p;
    cudaGetSymbolAddress(&p, g_scores); char* sc    = (char*)p;
    cudaGetSymbolAddress(&p, g_ppk);    char* ppk   = (char*)p;
    cudaGetSymbolAddress(&p, g_apk);    char* apk   = (char*)p;
    cudaGetSymbolAddress(&p, g_hpk);    char* hpk   = (char*)p;

    const long WPL  = (long)DIM * DIM * 2;
    const long QKVP = (long)MTOT * DIM * 2;
    char* qpk = qkvpk;
    char* kpk = qkvpk + QKVP;
    char* vpk = qkvpk + 2 * QKVP;

    k_pack<<<dim3((MTOT * DIM) / (8 * 256)), 256>>>(x, xpk, DIM);
    k_wtrans<<<dim3(32, 64, 5), 256>>>(Wq, Wk, Wv, W1, W2, wpk, w1pk, w2pk);

    // q,k,v = x @ W{q,k,v} in one launch (HALF out)
    gemm_mma<0><<<dim3(16, 64, 3), 256, GEMM_SMEM>>>(
        xpk, wpk, DIM * 2, DIM * 2, 0, WPL, 32,
        0, 0, 0, 0, 0,
        qkvpk, QKVP, 0, DIM * 2,
        1.0f, 0, 16);

    // scores = q k^T / 32 (fp16 out; TRIANGULAR grid: 272 live tiles/batch)
    gemm_mma<0><<<dim3(272, 1, BSZ), 256, GEMM_SMEM>>>(
        qpk, kpk, DIM * 2, DIM * 2,
        (long)SEQ * DIM * 2, (long)SEQ * DIM * 2, 32,
        0, 0, 0, 0, 0,
        sc, (long)SEQ * SEQ * 2, 0, SEQ * 2,
        0.03125f, 0, 32 | 16);
    k_softmax<<<dim3(BSZ * SEQ), 256>>>();

    // attn = probs @ v  (B read NN from v's natural [s][d] layout; k-limit)
    gemm_mma<1><<<dim3(16, 16, BSZ), 256, GEMM_SMEM>>>(
        ppk, vpk, SEQ * 2, DIM * 2, (long)SEQ * SEQ * 2, (long)SEQ * DIM * 2, 64,
        0, 0, 0, 0, 0,
        apk, (long)SEQ * DIM * 2, 0, DIM * 2,
        1.0f, 0, 4 | 16);
    // h = relu([attn|x] @ W1 + b1)
    gemm_mma<0><<<dim3(16, 64, 1), 256, GEMM_SMEM>>>(
        apk, w1pk, DIM * 2, 2 * DIM * 2, 0, 0, 32,
        xpk, w1pk + 2048, DIM * 2, 2 * DIM * 2, 32,
        hpk, 0, 0, DIM * 2,
        1.0f, b1, 1 | 16);
    // out = h @ W2 + b2 (fp32 out)
    gemm_mma<0><<<dim3(16, 64, 1), 256, GEMM_SMEM>>>(
        hpk, w2pk, DIM * 2, DIM * 2, 0, 0, 32,
        0, 0, 0, 0, 0,
        out, 0, DIM, 0,
        1.0f, b2, 0);
}

// round 17
// speedup vs baseline: 1.0395x; 1.0395x over previous
#include <cuda_runtime.h>
#include <cuda_fp16.h>
#include <cstdint>

#define BSZ 4
#define SEQ 2048
#define DIM 1024
#define MTOT (BSZ*SEQ)

// ---------------------------------------------------------------------------
// HALF packed layout everywhere: per row of K floats, K/32 chunks of 64B
// [32 fp16], row stride K*2 bytes.
// ---------------------------------------------------------------------------
__device__ __align__(128) char g_xpk   [(size_t)MTOT * DIM * 2];
__device__ __align__(128) char g_wpk   [(size_t)3 * DIM * DIM * 2];
__device__ __align__(128) char g_w1pk  [(size_t)DIM * 2 * DIM * 2];
__device__ __align__(128) char g_w2pk  [(size_t)DIM * DIM * 2];
__device__ __align__(128) char g_qkvpk [(size_t)3 * MTOT * DIM * 2];  // q|k|v
__device__ __align__(128) char g_scores[(size_t)BSZ * SEQ * SEQ * 2]; // fp16
__device__ __align__(128) char g_ppk   [(size_t)BSZ * SEQ * SEQ * 2];
__device__ __align__(128) char g_apk   [(size_t)MTOT * DIM * 2];
__device__ __align__(128) char g_hpk   [(size_t)MTOT * DIM * 2];

// ---------------------------------------------------------------------------
// Helpers
// ---------------------------------------------------------------------------
__device__ __forceinline__ uint32_t smem_u32(const void* p) {
    uint32_t a;
    asm("{ .reg .u64 t; cvta.to.shared.u64 t, %1; cvt.u32.u64 %0, t; }" : "=r"(a) : "l"(p));
    return a;
}
__device__ __forceinline__ uint32_t swz(uint32_t x) { return x ^ ((x >> 3) & 0x70); }

__device__ __forceinline__ uint32_t f16pair(float v0, float v1) {
    uint32_t r;   // low16 = fp16(v0), high16 = fp16(v1)
    asm("cvt.rn.f16x2.f32 %0, %1, %2;" : "=r"(r) : "f"(v1), "f"(v0));
    return r;
}
__device__ __forceinline__ void ldsm4(uint32_t* r, uint32_t addr) {
    asm volatile("ldmatrix.sync.aligned.m8n8.x4.shared.b16 {%0,%1,%2,%3}, [%4];"
                 : "=r"(r[0]), "=r"(r[1]), "=r"(r[2]), "=r"(r[3]) : "r"(addr));
}
__device__ __forceinline__ void ldsm4t(uint32_t* r, uint32_t addr) {
    asm volatile("ldmatrix.sync.aligned.m8n8.x4.trans.shared.b16 {%0,%1,%2,%3}, [%4];"
                 : "=r"(r[0]), "=r"(r[1]), "=r"(r[2]), "=r"(r[3]) : "r"(addr));
}
__device__ __forceinline__ void mma_f16(float* d, const uint32_t* a, const uint32_t* b) {
    asm volatile(
        "mma.sync.aligned.m16n8k16.row.col.f32.f16.f16.f32 "
        "{%0,%1,%2,%3}, {%4,%5,%6,%7}, {%8,%9}, {%0,%1,%2,%3};"
        : "+f"(d[0]), "+f"(d[1]), "+f"(d[2]), "+f"(d[3])
        : "r"(a[0]), "r"(a[1]), "r"(a[2]), "r"(a[3]), "r"(b[0]), "r"(b[1]));
}

// ---------------------------------------------------------------------------
// NT GEMM, 128(M)x64(N) tile, 8 warps (32x32 each), pure fp16 operands,
// fp32 accumulate. 3-stage cp.async pipeline, 1 sync/chunk.
// BNN=0: B source K-major [n][k] (ldmatrix); BNN=1: B row-major [k][n]
//        (ldmatrix.trans; B tile = 32 k-rows x 128B contiguous n)
// mode: 1=relu, 2=causal block skip, 4=causal k-limit, 16=half packed out
// ---------------------------------------------------------------------------
#define TA_BYTES 16384
#define STG 24576
#define GEMM_SMEM (3 * STG)

template <int BNN>
__global__ __launch_bounds__(256, 3) void gemm_mma(
    const char* __restrict__ Ap, const char* __restrict__ Bp,
    long aRB, long bRB, long zsA, long zsB, int kc1,
    const char* __restrict__ Ap2, const char* __restrict__ Bp2,
    long aRB2, long bRB2, int kc2,
    void* Cout, long zsC, int ldc, long cRB,
    float scale, const float* __restrict__ bias, int mode)
{
    int m0 = blockIdx.y * 128, n0 = blockIdx.x * 64;
    if ((mode & 2) && n0 >= m0 + 128) return;
    if (mode & 4) { int ke = (m0 + 128) >> 5; if (ke < kc1) kc1 = ke; }
    int z = blockIdx.z;
    Ap += (long)z * zsA;
    Bp += (long)z * zsB;
    char* Cb = (char*)Cout + (long)z * zsC;

    extern __shared__ char smem[];
    uint32_t sb = smem_u32(smem);
    int tid = threadIdx.x;
    int nch = kc1 + kc2;

    auto issue = [&](int c) {
        uint32_t stg = sb + (uint32_t)(c % 3) * STG;
        int cc = c;
        const char* pa; const char* pb; long ra, rb;
        if (c < kc1) { pa = Ap;  pb = Bp;  ra = aRB;  rb = bRB; }
        else         { pa = Ap2; pb = Bp2; ra = aRB2; rb = bRB2; cc = c - kc1; }
        long cOff = (long)cc * 64;
#pragma unroll
        for (int j = 0; j < 3; j++) {
            int slot = tid + j * 256;
            const char* g; uint32_t d;
            if (slot < 512) {
                int row = slot >> 2, seg = slot & 3;
                g = pa + (long)(m0 + row) * ra + cOff + seg * 16;
                d = stg + swz((uint32_t)(row * 128 + seg * 16));
            } else if (BNN) {
                int local = slot - 512;
                int row = local >> 3, seg = local & 7;
                g = pb + (long)(cc * 32 + row) * rb + (long)n0 * 2 + seg * 16;
                d = stg + (uint32_t)TA_BYTES + swz((uint32_t)(row * 128 + seg * 16));
            } else {
                int local = slot - 512;
                int row = local >> 2, seg = local & 3;
                g = pb + (long)(n0 + row) * rb + cOff + seg * 16;
                d = stg + (uint32_t)TA_BYTES + swz((uint32_t)(row * 128 + seg * 16));
            }
            asm volatile("cp.async.cg.shared.global [%0], [%1], 16;" :: "r"(d), "l"(g));
        }
        asm volatile("cp.async.commit_group;" ::: "memory");
    };

    int wid = tid >> 5, lane = tid & 31;
    int wm = wid >> 1, wn = wid & 1;   // 4 (m) x 2 (n) warps
    float acc[2][4][4] = {};

    issue(0);
    if (nch > 1) issue(1);
    else asm volatile("cp.async.commit_group;" ::: "memory");

    uint32_t aRowLoc = (uint32_t)((wm * 32 + (lane & 15)) * 128 + ((lane >> 4) << 4));
    int bg = lane >> 3;
    uint32_t bRowLoc = (uint32_t)((wn * 32 + (lane & 7) + ((bg >> 1) << 3)) * 128 + ((bg & 1) << 4));
    uint32_t bRowLocT = (uint32_t)((((lane >> 3) & 1) * 8 + (lane & 7)) * 128
                                   + wn * 64 + ((lane >> 4) << 4));

    for (int c = 0; c < nch; c++) {
        asm volatile("cp.async.wait_group 1;" ::: "memory");
        __syncthreads();
        if (c + 2 < nch) issue(c + 2);
        else asm volatile("cp.async.commit_group;" ::: "memory");

        uint32_t ta = sb + (uint32_t)(c % 3) * STG;
        uint32_t tb = ta + TA_BYTES;
#pragma unroll
        for (int s = 0; s < 2; s++) {
            int ko = s * 32;
            uint32_t Ah[2][4], Bh[2][4];
#pragma unroll
            for (int mt = 0; mt < 2; mt++)
                ldsm4(Ah[mt], ta + swz(aRowLoc + mt * 2048 + ko));
#pragma unroll
            for (int bt = 0; bt < 2; bt++) {
                if (BNN) ldsm4t(Bh[bt], tb + swz(bRowLocT + s * 2048 + bt * 32));
                else     ldsm4 (Bh[bt], tb + swz(bRowLoc + bt * 2048 + ko));
            }
#pragma unroll
            for (int mt = 0; mt < 2; mt++)
#pragma unroll
                for (int nt = 0; nt < 4; nt++)
                    mma_f16(acc[mt][nt], Ah[mt], &Bh[nt >> 1][(nt & 1) * 2]);
        }
    }

    // Epilogue
    int ql = lane & 3;
    int r0 = m0 + wm * 32 + (lane >> 2);
    if (mode & 16) {           // half packed out
        int cw = (n0 + wn * 32) >> 5;
        char* cbase = Cb + (long)cw * 64;
#pragma unroll
        for (int mt = 0; mt < 2; mt++) {
#pragma unroll
            for (int half = 0; half < 2; half++) {
                long row = r0 + mt * 16 + half * 8;
                char* rp = cbase + row * cRB;
#pragma unroll
                for (int nt = 0; nt < 4; nt++) {
                    float v0 = acc[mt][nt][half * 2 + 0] * scale;
                    float v1 = acc[mt][nt][half * 2 + 1] * scale;
                    int col = n0 + wn * 32 + nt * 8 + ql * 2;
                    if (bias) { v0 += bias[col]; v1 += bias[col + 1]; }
                    if (mode & 1) { v0 = fmaxf(v0, 0.f); v1 = fmaxf(v1, 0.f); }
                    *(uint32_t*)(rp + (nt * 8 + ql * 2) * 2) = f16pair(v0, v1);
                }
            }
        }
    } else {                   // fp32 out
        float* Cf = (float*)Cb;
#pragma unroll
        for (int mt = 0; mt < 2; mt++) {
#pragma unroll
            for (int half = 0; half < 2; half++) {
                long row = r0 + mt * 16 + half * 8;
#pragma unroll
                for (int nt = 0; nt < 4; nt++) {
                    float v0 = acc[mt][nt][half * 2 + 0] * scale;
                    float v1 = acc[mt][nt][half * 2 + 1] * scale;
                    int col = n0 + wn * 32 + nt * 8 + ql * 2;
                    if (bias) { v0 += bias[col]; v1 += bias[col + 1]; }
                    if (mode & 1) { v0 = fmaxf(v0, 0.f); v1 = fmaxf(v1, 0.f); }
                    *(float2*)(Cf + row * (long)ldc + col) = make_float2(v0, v1);
                }
            }
        }
    }
}

// ---------------------------------------------------------------------------
// Pack fp32 [rows][K] -> HALF packed
// ---------------------------------------------------------------------------
__global__ __launch_bounds__(256) void k_pack(const float* __restrict__ src,
                                              char* __restrict__ dst, int K) {
    long j0 = ((long)blockIdx.x * 256 + threadIdx.x) * 8;
    float4 f0 = *(const float4*)(src + j0);
    float4 f1 = *(const float4*)(src + j0 + 4);
    long row = j0 / K;
    int k0 = (int)(j0 - row * K);
    uint32_t h0 = f16pair(f0.x, f0.y), h1 = f16pair(f0.z, f0.w);
    uint32_t h2 = f16pair(f1.x, f1.y), h3 = f16pair(f1.z, f1.w);
    char* p = dst + row * (long)K * 2 + (k0 >> 5) * 64 + (k0 & 31) * 2;
    *(uint4*)p = make_uint4(h0, h1, h2, h3);
}

// ---------------------------------------------------------------------------
// ALL weight transposes in one launch (z: 0-2 Wq/Wk/Wv, 3 W2, 4 W1)
// ---------------------------------------------------------------------------
__global__ __launch_bounds__(256) void k_wtrans(
    const float* __restrict__ Wq, const float* __restrict__ Wk,
    const float* __restrict__ Wv, const float* __restrict__ W1,
    const float* __restrict__ W2,
    char* __restrict__ wpk, char* __restrict__ w1pk, char* __restrict__ w2pk)
{
    const long WPL = (long)DIM * DIM * 2;
    int z = blockIdx.z;
    const float* in; char* out; int R;
    if (z == 0)      { in = Wq; out = wpk;           R = DIM; }
    else if (z == 1) { in = Wk; out = wpk + WPL;     R = DIM; }
    else if (z == 2) { in = Wv; out = wpk + 2 * WPL; R = DIM; }
    else if (z == 3) { in = W2; out = w2pk;          R = DIM; }
    else             { in = W1; out = w1pk;          R = 2 * DIM; }
    int r0 = blockIdx.y * 32;
    if (r0 >= R) return;
    int c0 = blockIdx.x * 32;

    __shared__ float t[32][33];
    int tx = threadIdx.x & 31, ty = threadIdx.x >> 5;
#pragma unroll
    for (int i = ty; i < 32; i += 8)
        t[i][tx] = in[(long)(r0 + i) * DIM + c0 + tx];
    __syncthreads();
    int i = threadIdx.x >> 3;
    int g = (threadIdx.x & 7) * 4;
    float v0 = t[g + 0][i], v1 = t[g + 1][i], v2 = t[g + 2][i], v3 = t[g + 3][i];
    uint32_t h0 = f16pair(v0, v1), h1 = f16pair(v2, v3);
    char* p = out + (long)(c0 + i) * ((long)R * 2) + (r0 >> 5) * 64 + g * 2;
    *(uint2*)p = make_uint2(h0, h1);
}

// ---------------------------------------------------------------------------
// Causal softmax: 2 rows per block (128 threads each, 16 fp16/thread).
// HALF packed scores row -> HALF packed probs row.
// ---------------------------------------------------------------------------
__global__ __launch_bounds__(256) void k_softmax() {
    int half = threadIdx.x >> 7;            // which of the 2 rows
    int tid = threadIdx.x & 127;            // lane within row group
    long rowi = (long)blockIdx.x * 2 + half;
    const char* p = g_scores + rowi * (SEQ * 2);
    char* dst = g_ppk + rowi * (SEQ * 2);
    int cnt = (int)(rowi & (SEQ - 1)) + 1;
    int j0 = tid * 16;
    __shared__ float red[2][128];

    uint4 raw0 = *(const uint4*)(p + (j0 >> 5) * 64 + (j0 & 31) * 2);
    uint4 raw1 = *(const uint4*)(p + ((j0 + 8) >> 5) * 64 + ((j0 + 8) & 31) * 2);
    __half* h0p = (__half*)&raw0;
    __half* h1p = (__half*)&raw1;
    float v[16];
    float m = -3.4e38f;
#pragma unroll
    for (int i = 0; i < 8; i++) {
        v[i]     = (j0 + i < cnt)     ? __half2float(h0p[i]) : -3.4e38f;
        v[8 + i] = (j0 + 8 + i < cnt) ? __half2float(h1p[i]) : -3.4e38f;
    }
#pragma unroll
    for (int i = 0; i < 16; i++) m = fmaxf(m, v[i]);
    red[half][tid] = m;
    __syncthreads();
    for (int s = 64; s > 0; s >>= 1) {
        if (tid < s) red[half][tid] = fmaxf(red[half][tid], red[half][tid + s]);
        __syncthreads();
    }
    m = red[half][0];
    __syncthreads();
    float sum = 0.f;
#pragma unroll
    for (int i = 0; i < 16; i++) {
        int j = j0 + (i < 8 ? i : i); // index base handled below
    }
#pragma unroll
    for (int i = 0; i < 8; i++) {
        v[i]     = (j0 + i < cnt)     ? __expf(v[i] - m)     : 0.f;
        v[8 + i] = (j0 + 8 + i < cnt) ? __expf(v[8 + i] - m) : 0.f;
        sum += v[i] + v[8 + i];
    }
    red[half][tid] = sum;
    __syncthreads();
    for (int s = 64; s > 0; s >>= 1) {
        if (tid < s) red[half][tid] += red[half][tid + s];
        __syncthreads();
    }
    float inv = 1.0f / red[half][0];
#pragma unroll
    for (int i = 0; i < 16; i++) v[i] *= inv;

    uint32_t a0 = f16pair(v[0], v[1]),  a1 = f16pair(v[2], v[3]);
    uint32_t a2 = f16pair(v[4], v[5]),  a3 = f16pair(v[6], v[7]);
    uint32_t b0 = f16pair(v[8], v[9]),  b1 = f16pair(v[10], v[11]);
    uint32_t b2 = f16pair(v[12], v[13]), b3 = f16pair(v[14], v[15]);
    *(uint4*)(dst + (j0 >> 5) * 64 + (j0 & 31) * 2) = make_uint4(a0, a1, a2, a3);
    *(uint4*)(dst + ((j0 + 8) >> 5) * 64 + ((j0 + 8) & 31) * 2) = make_uint4(b0, b1, b2, b3);
}

// ---------------------------------------------------------------------------
// Launch
// ---------------------------------------------------------------------------
extern "C" void kernel_launch(void* const* d_in, const int* in_sizes, int n_in,
                              void* d_out, int out_size) {
    const float* x  = (const float*)d_in[0];
    const float* Wq = (const float*)d_in[1];
    const float* Wk = (const float*)d_in[2];
    const float* Wv = (const float*)d_in[3];
    const float* W1 = (const float*)d_in[4];
    const float* b1 = (const float*)d_in[5];
    const float* W2 = (const float*)d_in[6];
    const float* b2 = (const float*)d_in[7];
    float* out = (float*)d_out;

    cudaFuncSetAttribute(gemm_mma<0>, cudaFuncAttributeMaxDynamicSharedMemorySize, GEMM_SMEM);
    cudaFuncSetAttribute(gemm_mma<1>, cudaFuncAttributeMaxDynamicSharedMemorySize, GEMM_SMEM);

    void* p;
    cudaGetSymbolAddress(&p, g_xpk);    char* xpk   = (char*)p;
    cudaGetSymbolAddress(&p, g_wpk);    char* wpk   = (char*)p;
    cudaGetSymbolAddress(&p, g_w1pk);   char* w1pk  = (char*)p;
    cudaGetSymbolAddress(&p, g_w2pk);   char* w2pk  = (char*)p;
    cudaGetSymbolAddress(&p, g_qkvpk);  char* qkvpk = (char*)p;
    cudaGetSymbolAddress(&p, g_scores); char* sc    = (char*)p;
    cudaGetSymbolAddress(&p, g_ppk);    char* ppk   = (char*)p;
    cudaGetSymbolAddress(&p, g_apk);    char* apk   = (char*)p;
    cudaGetSymbolAddress(&p, g_hpk);    char* hpk   = (char*)p;

    const long WPL  = (long)DIM * DIM * 2;
    const long QKVP = (long)MTOT * DIM * 2;
    char* qpk = qkvpk;
    char* kpk = qkvpk + QKVP;
    char* vpk = qkvpk + 2 * QKVP;

    k_pack<<<dim3((MTOT * DIM) / (8 * 256)), 256>>>(x, xpk, DIM);
    k_wtrans<<<dim3(32, 64, 5), 256>>>(Wq, Wk, Wv, W1, W2, wpk, w1pk, w2pk);

    // q,k,v = x @ W{q,k,v} in one launch (HALF out)
    gemm_mma<0><<<dim3(16, 64, 3), 256, GEMM_SMEM>>>(
        xpk, wpk, DIM * 2, DIM * 2, 0, WPL, 32,
        0, 0, 0, 0, 0,
        qkvpk, QKVP, 0, DIM * 2,
        1.0f, 0, 16);

    // scores = q k^T / 32 (fp16 out; 2D grid with causal block skip)
    gemm_mma<0><<<dim3(32, 16, BSZ), 256, GEMM_SMEM>>>(
        qpk, kpk, DIM * 2, DIM * 2,
        (long)SEQ * DIM * 2, (long)SEQ * DIM * 2, 32,
        0, 0, 0, 0, 0,
        sc, (long)SEQ * SEQ * 2, 0, SEQ * 2,
        0.03125f, 0, 2 | 16);
    k_softmax<<<dim3(BSZ * SEQ / 2), 256>>>();

    // attn = probs @ v  (B read NN from v's natural [s][d] layout; k-limit)
    gemm_mma<1><<<dim3(16, 16, BSZ), 256, GEMM_SMEM>>>(
        ppk, vpk, SEQ * 2, DIM * 2, (long)SEQ * SEQ * 2, (long)SEQ * DIM * 2, 64,
        0, 0, 0, 0, 0,
        apk, (long)SEQ * DIM * 2, 0, DIM * 2,
        1.0f, 0, 4 | 16);
    // h = relu([attn|x] @ W1 + b1)
    gemm_mma<0><<<dim3(16, 64, 1), 256, GEMM_SMEM>>>(
        apk, w1pk, DIM * 2, 2 * DIM * 2, 0, 0, 32,
        xpk, w1pk + 2048, DIM * 2, 2 * DIM * 2, 32,
        hpk, 0, 0, DIM * 2,
        1.0f, b1, 1 | 16);
    // out = h @ W2 + b2 (fp32 out)
    gemm_mma<0><<<dim3(16, 64, 1), 256, GEMM_SMEM>>>(
        hpk, w2pk, DIM * 2, DIM * 2, 0, 0, 32,
        0, 0, 0, 0, 0,
        out, 0, DIM, 0,
        1.0f, b2, 0);
}